// round 6
// baseline (speedup 1.0000x reference)
#include <cuda_runtime.h>
#include <cuda_bf16.h>
#include <math.h>
#include <stdint.h>

#define Bn   4
#define Tn   256
#define Vn   1024
#define Sn   64
#define DIMn 1024
#define CVn  256
#define BT   (Bn*Tn)          // 1024
#define SW   72               // smem word stride (conflict-free fragment LDS)

// ---------------- scratch ----------------
__device__ float g_pp[2][4][CVn*DIMn];     // k1 split-K partials
__device__ float g_Wuk[CVn*DIMn];
__device__ float g_Wuv[CVn*DIMn];
__device__ float g_bias_part[2][16][DIMn];
__device__ float g_buk[DIMn];
__device__ float g_buv[DIMn];
__device__ int   g_idx[BT*Sn];
__device__ float g_Ppart[4][BT*CVn];       // k2b split-K partials
__device__ float g_wpp[2][BT*CVn];         // attn halves: sum_s e_s * vg_s
__device__ float g_alphap[2][BT];          // attn halves: sum_s e_s
__device__ float g_opart[2][BT*DIMn];      // k6 split-K partials

// ---------------- bf16 helpers ----------------
__device__ __forceinline__ uint32_t packbf(float x, float y) {
    __nv_bfloat162 h = __floats2bfloat162_rn(x, y);
    return *reinterpret_cast<uint32_t*>(&h);
}
__device__ __forceinline__ void mma_bf16(float c[4], const uint32_t a[4], const uint32_t b[2]) {
    asm volatile("mma.sync.aligned.m16n8k16.row.col.f32.bf16.bf16.f32 "
        "{%0,%1,%2,%3}, {%4,%5,%6,%7}, {%8,%9}, {%0,%1,%2,%3};"
        : "+f"(c[0]), "+f"(c[1]), "+f"(c[2]), "+f"(c[3])
        : "r"(a[0]), "r"(a[1]), "r"(a[2]), "r"(a[3]), "r"(b[0]), "r"(b[1]));
}

// ---------------- bf16 64x64-tile GEMM body, 128 threads ----------------
// C = (A [+ A2]) * B over k0..k0+ksub ; A row stride Ks.
// B row-major [K,Nn] (TRANSB=0) or [N,Ks] (TRANSB=1).
template<int Nn, int Ks, bool TRANSB, bool DUALA>
__device__ __forceinline__ void gemm_bf16(
    const int m0, const int n0, const int k0, const int ksub,
    const float* __restrict__ A, const float* __restrict__ A2,
    const float* __restrict__ Bm, float* __restrict__ C,
    uint32_t Ap[2][8][SW], uint32_t Bp[2][8][SW])
{
    const int tid = threadIdx.x, lane = tid & 31, wid = tid >> 5;
    const int wm = (wid & 1) * 32, wn = (wid >> 1) * 32;
    const int am0 = tid >> 2,         ag0 = tid & 3;
    const int am1 = (tid + 128) >> 2, ag1 = (tid + 128) & 3;
    const int bk2 = tid >> 4,         bng = tid & 15;

    float acc[2][4][4];
    #pragma unroll
    for (int i = 0; i < 2; i++)
        #pragma unroll
        for (int j = 0; j < 4; j++)
            #pragma unroll
            for (int q = 0; q < 4; q++) acc[i][j][q] = 0.f;

    float4 ra0, ra1, rb0, rb1;

    auto loadg = [&](int kt) {
        const size_t o0 = (size_t)(m0 + am0)*Ks + k0 + kt + ag0*4;
        const size_t o1 = (size_t)(m0 + am1)*Ks + k0 + kt + ag1*4;
        ra0 = *(const float4*)(A + o0);
        ra1 = *(const float4*)(A + o1);
        if (DUALA) {
            float4 s0 = *(const float4*)(A2 + o0);
            float4 s1 = *(const float4*)(A2 + o1);
            ra0.x += s0.x; ra0.y += s0.y; ra0.z += s0.z; ra0.w += s0.w;
            ra1.x += s1.x; ra1.y += s1.y; ra1.z += s1.z; ra1.w += s1.w;
        }
        if (!TRANSB) {
            rb0 = *(const float4*)(Bm + (size_t)(k0 + kt + 2*bk2    )*Nn + n0 + bng*4);
            rb1 = *(const float4*)(Bm + (size_t)(k0 + kt + 2*bk2 + 1)*Nn + n0 + bng*4);
        } else {
            rb0 = *(const float4*)(Bm + (size_t)(n0 + am0)*Ks + k0 + kt + ag0*4);
            rb1 = *(const float4*)(Bm + (size_t)(n0 + am1)*Ks + k0 + kt + ag1*4);
        }
    };
    auto stores = [&](int buf) {
        Ap[buf][ag0*2    ][am0] = packbf(ra0.x, ra0.y);
        Ap[buf][ag0*2 + 1][am0] = packbf(ra0.z, ra0.w);
        Ap[buf][ag1*2    ][am1] = packbf(ra1.x, ra1.y);
        Ap[buf][ag1*2 + 1][am1] = packbf(ra1.z, ra1.w);
        if (!TRANSB) {
            uint4 q;
            q.x = packbf(rb0.x, rb1.x); q.y = packbf(rb0.y, rb1.y);
            q.z = packbf(rb0.z, rb1.z); q.w = packbf(rb0.w, rb1.w);
            *(uint4*)&Bp[buf][bk2][bng*4] = q;
        } else {
            Bp[buf][ag0*2    ][am0] = packbf(rb0.x, rb0.y);
            Bp[buf][ag0*2 + 1][am0] = packbf(rb0.z, rb0.w);
            Bp[buf][ag1*2    ][am1] = packbf(rb1.x, rb1.y);
            Bp[buf][ag1*2 + 1][am1] = packbf(rb1.z, rb1.w);
        }
    };

    loadg(0); stores(0); __syncthreads();
    const int niter = ksub >> 4;
    for (int it = 0; it < niter; it++) {
        const int buf = it & 1;
        const bool nxt = (it + 1 < niter);
        if (nxt) loadg((it + 1) << 4);

        uint32_t af[2][4], bfr[4][2];
        #pragma unroll
        for (int mi = 0; mi < 2; mi++) {
            const int row = wm + mi*16 + (lane >> 2);
            af[mi][0] = Ap[buf][    (lane & 3)][row];
            af[mi][1] = Ap[buf][    (lane & 3)][row + 8];
            af[mi][2] = Ap[buf][4 + (lane & 3)][row];
            af[mi][3] = Ap[buf][4 + (lane & 3)][row + 8];
        }
        #pragma unroll
        for (int ni = 0; ni < 4; ni++) {
            const int col = wn + ni*8 + (lane >> 2);
            bfr[ni][0] = Bp[buf][    (lane & 3)][col];
            bfr[ni][1] = Bp[buf][4 + (lane & 3)][col];
        }
        #pragma unroll
        for (int mi = 0; mi < 2; mi++)
            #pragma unroll
            for (int ni = 0; ni < 4; ni++)
                mma_bf16(acc[mi][ni], af[mi], bfr[ni]);

        if (nxt) { stores(buf ^ 1); __syncthreads(); }
    }

    #pragma unroll
    for (int mi = 0; mi < 2; mi++) {
        const int r = m0 + wm + mi*16 + (lane >> 2);
        #pragma unroll
        for (int ni = 0; ni < 4; ni++) {
            const int c = n0 + wn + ni*8 + 2*(lane & 3);
            float2 o0, o1;
            o0.x = acc[mi][ni][0]; o0.y = acc[mi][ni][1];
            o1.x = acc[mi][ni][2]; o1.y = acc[mi][ni][3];
            *(float2*)(C + (size_t)r*Nn + c) = o0;
            *(float2*)(C + (size_t)(r + 8)*Nn + c) = o1;
        }
    }
}

// ---------------- prep: k1 partials (512) + bias partials (32) + build_idx (1024) ----------------
__global__ void __launch_bounds__(128)
prep_kernel(const float* __restrict__ Wu, const float* __restrict__ Wk,
            const float* __restrict__ Wv, const float* __restrict__ bu,
            const void* __restrict__ maskp) {
    __shared__ __align__(16) uint32_t Ap[2][8][SW];
    __shared__ __align__(16) uint32_t Bp[2][8][SW];
    const int bid = blockIdx.x;
    const int tid = threadIdx.x;

    if (bid < 512) {
        const int z = bid >> 8, r = bid & 255;
        const int ks = r >> 6, t = r & 63;
        const int m0 = (t >> 4) * 64, n0 = (t & 15) * 64;
        gemm_bf16<DIMn, DIMn, false, false>(m0, n0, ks*256, 256, Wu, nullptr,
                                            z ? Wv : Wk, g_pp[z][ks], Ap, Bp);
    } else if (bid < 544) {
        const int r = bid - 512;
        const int z = r & 1, slice = r >> 1;
        const float* W = z ? Wv : Wk;
        const int d0 = slice * 64;
        __shared__ float sbu[64];
        if (tid < 64) sbu[tid] = bu[d0 + tid];
        __syncthreads();
        float acc[8];
        #pragma unroll
        for (int k = 0; k < 8; k++) acc[k] = 0.f;
        for (int dd = 0; dd < 64; dd++) {
            const float bv = sbu[dd];
            const float* row = W + (size_t)(d0 + dd)*DIMn + tid;
            #pragma unroll
            for (int k = 0; k < 8; k++) acc[k] += bv * row[128*k];
        }
        #pragma unroll
        for (int k = 0; k < 8; k++) g_bias_part[z][slice][tid + 128*k] = acc[k];
    } else {
        const int bt = bid - 544, b = bt >> 8, t = bt & 255;
        const int lane = tid & 31, wid = tid >> 5;
        const unsigned char* m8 = (const unsigned char*)maskp;
        const int* m32 = (const int*)maskp;

        int dsum = 0;
        #pragma unroll
        for (int u = 0; u < 8; u++) dsum += (m8[(tid*8 + u)*4 + 1] != 0);
        const bool u8 = (__syncthreads_or(dsum) != 0);

        int flags = 0, cnt = 0;
        #pragma unroll
        for (int u = 0; u < 8; u++) {
            const int v = tid*8 + u;
            const int e = (b*Vn + v)*Tn + t;
            const int mm = u8 ? (int)m8[e] : (m32[e] != 0);
            if (mm) { flags |= (1 << u); cnt++; }
        }
        int val = cnt;
        #pragma unroll
        for (int off = 1; off < 32; off <<= 1) {
            int vv = __shfl_up_sync(0xffffffffu, val, off);
            if (lane >= off) val += vv;
        }
        __shared__ int wtot[4];
        if (lane == 31) wtot[wid] = val;
        __syncthreads();
        int woff = 0, total = 0;
        #pragma unroll
        for (int w = 0; w < 4; w++) { int tw = wtot[w]; if (w < wid) woff += tw; total += tw; }
        int pos = woff + val - cnt;
        #pragma unroll
        for (int u = 0; u < 8; u++)
            if (flags & (1 << u)) { if (pos < Sn) g_idx[bt*Sn + pos] = tid*8 + u; pos++; }
        if (tid == 0)
            for (int p = total; p < Sn; p++) g_idx[bt*Sn + p] = Vn;
    }
}

// ---------------- combine: Wuk/Wuv (512) + buk/buv (2) ----------------
__global__ void __launch_bounds__(128)
combine_kernel() {
    const int bid = blockIdx.x, tid = threadIdx.x;
    if (bid < 512) {
        #pragma unroll
        for (int h = 0; h < 2; h++) {
            const int F = bid*256 + h*128 + tid;
            const int z = F >> 16, off4 = F & 65535;
            float4 s = make_float4(0.f, 0.f, 0.f, 0.f);
            #pragma unroll
            for (int p = 0; p < 4; p++) {
                float4 v = ((const float4*)g_pp[z][p])[off4];
                s.x += v.x; s.y += v.y; s.z += v.z; s.w += v.w;
            }
            ((float4*)(z ? g_Wuv : g_Wuk))[off4] = s;
        }
    } else {
        const int z = bid - 512;
        #pragma unroll
        for (int h = 0; h < 8; h++) {
            const int j = h*128 + tid;
            float a = 0.f;
            #pragma unroll
            for (int p = 0; p < 16; p++) a += g_bias_part[z][p][j];
            (z ? g_buv : g_buk)[j] = a;
        }
    }
}

// ---------------- k2b: P partials, split-K x4 (256 blocks) ----------------
__global__ void __launch_bounds__(128)
k2b_kernel(const float* __restrict__ x) {
    __shared__ __align__(16) uint32_t Ap[2][8][SW];
    __shared__ __align__(16) uint32_t Bp[2][8][SW];
    const int bid = blockIdx.x;
    const int ks = bid >> 6, r = bid & 63;
    const int m0 = (r >> 2) * 64, n0 = (r & 3) * 64;
    gemm_bf16<CVn, DIMn, true, false>(m0, n0, ks*256, 256, x, nullptr,
                                      g_Wuk, g_Ppart[ks], Ap, Bp);
}

// ---------------- attn: 2 CTAs per (b,t), each 32 s-rows ----------------
#define VPAD 272
__global__ void __launch_bounds__(256)
attn_kernel(const float* __restrict__ x, const float* __restrict__ vision) {
    __shared__ __align__(16) float vg[32][VPAD];
    __shared__ __align__(16) float P_s[CVn];
    __shared__ float e_s[32];
    __shared__ int   idx_s[32];
    __shared__ float red_s[8];
    __shared__ float bq_sh;

    const int bt = blockIdx.x >> 1, half = blockIdx.x & 1;
    const int b = bt >> 8, tid = threadIdx.x;
    const int lane = tid & 31, wid = tid >> 5;
    const int c0 = half * 32;

    P_s[tid] = g_Ppart[0][bt*CVn + tid] + g_Ppart[1][bt*CVn + tid]
             + g_Ppart[2][bt*CVn + tid] + g_Ppart[3][bt*CVn + tid];
    if (tid < 32) idx_s[tid] = g_idx[bt*Sn + c0 + tid];
    {
        float4 xv = *(const float4*)(x + (size_t)bt*DIMn + tid*4);
        float4 bv = *(const float4*)(g_buk + tid*4);
        float a = xv.x*bv.x + xv.y*bv.y + xv.z*bv.z + xv.w*bv.w;
        #pragma unroll
        for (int off = 16; off; off >>= 1) a += __shfl_down_sync(0xffffffffu, a, off);
        if (lane == 0) red_s[wid] = a;
    }
    __syncthreads();
    if (tid == 0) {
        float s = 0.f;
        #pragma unroll
        for (int w = 0; w < 8; w++) s += red_s[w];
        bq_sh = s;
    }
    __syncthreads();
    const float bq = bq_sh;

    // gather 32 rows
    #pragma unroll
    for (int i = 0; i < 8; i++) {
        const int L = tid + 256*i;             // 0..2047 float4 slots
        const int s = L >> 6, c4 = L & 63;
        const int idx = idx_s[s];
        float4 v = make_float4(0.f, 0.f, 0.f, 0.f);
        if (idx < Vn)
            v = *(const float4*)(vision + ((size_t)(b*Vn + idx))*CVn + c4*4);
        *(float4*)&vg[s][c4*4] = v;
    }
    __syncthreads();

    // dot + exp: 8 lanes per row
    {
        const int sg = tid >> 3, l8 = tid & 7;
        float a = 0.f;
        #pragma unroll
        for (int i = 0; i < 8; i++) {
            const int c4 = l8 + 8*i;
            float4 vv = *(const float4*)&vg[sg][c4*4];
            float4 pp = *(const float4*)&P_s[c4*4];
            a += vv.x*pp.x + vv.y*pp.y + vv.z*pp.z + vv.w*pp.w;
        }
        a += __shfl_down_sync(0xffffffffu, a, 4, 8);
        a += __shfl_down_sync(0xffffffffu, a, 2, 8);
        a += __shfl_down_sync(0xffffffffu, a, 1, 8);
        if (l8 == 0) {
            const int idx = idx_s[sg];
            float lp = (a + bq) * 0.03125f + (idx < Vn ? 0.f : 100.f);
            e_s[sg] = __expf(fminf(lp, 80.f));
        }
    }
    __syncthreads();

    float acc_c = 0.f;
    #pragma unroll 8
    for (int s = 0; s < 32; s++)
        acc_c += e_s[s] * vg[s][tid];
    g_wpp[half][bt*CVn + tid] = acc_c;

    if (tid < 32) {
        float a = e_s[tid];
        #pragma unroll
        for (int off = 16; off; off >>= 1) a += __shfl_down_sync(0xffffffffu, a, off);
        if (tid == 0) g_alphap[half][bt] = a;
    }
}

// ---------------- k6part: out-GEMM partials split-K x2 (512), A = wp0+wp1 ----------------
__global__ void __launch_bounds__(128)
k6part_kernel() {
    __shared__ __align__(16) uint32_t Ap[2][8][SW];
    __shared__ __align__(16) uint32_t Bp[2][8][SW];
    const int bid = blockIdx.x;
    const int ks = bid >> 8, r = bid & 255;
    const int m0 = (r >> 4) * 64, n0 = (r & 15) * 64;
    gemm_bf16<DIMn, CVn, false, true>(m0, n0, ks*128, 128, g_wpp[0], g_wpp[1],
                                      g_Wuv, g_opart[ks], Ap, Bp);
}

// ---------------- finish: out = (p0+p1 + alpha*buv)/Z_b + x ----------------
__global__ void __launch_bounds__(256)
finish_kernel(const float* __restrict__ x, float* __restrict__ out) {
    const int r = blockIdx.x, b = r >> 8, tid = threadIdx.x;
    const int lane = tid & 31, wid = tid >> 5;
    __shared__ float zr[8];

    float a = g_alphap[0][b*256 + tid] + g_alphap[1][b*256 + tid];
    #pragma unroll
    for (int off = 16; off; off >>= 1) a += __shfl_down_sync(0xffffffffu, a, off);
    if (lane == 0) zr[wid] = a;
    __syncthreads();
    const float Z = zr[0] + zr[1] + zr[2] + zr[3] + zr[4] + zr[5] + zr[6] + zr[7];
    const float iz = 1.0f / Z;

    const float al = g_alphap[0][r] + g_alphap[1][r];
    float4 p0 = ((const float4*)g_opart[0])[r*256 + tid];
    float4 p1 = ((const float4*)g_opart[1])[r*256 + tid];
    float4 bv = ((const float4*)g_buv)[tid];
    float4 xv = ((const float4*)x)[r*256 + tid];
    float4 o;
    o.x = (p0.x + p1.x + al*bv.x)*iz + xv.x;
    o.y = (p0.y + p1.y + al*bv.y)*iz + xv.y;
    o.z = (p0.z + p1.z + al*bv.z)*iz + xv.z;
    o.w = (p0.w + p1.w + al*bv.w)*iz + xv.w;
    ((float4*)out)[r*256 + tid] = o;
}

// ---------------- launch ----------------
extern "C" void kernel_launch(void* const* d_in, const int* in_sizes, int n_in,
                              void* d_out, int out_size) {
    const float* x      = (const float*)d_in[0];
    const float* vision = (const float*)d_in[1];
    const void*  mask   = d_in[2];
    const float* Wu     = (const float*)d_in[3];
    const float* bu     = (const float*)d_in[4];
    const float* Wk     = (const float*)d_in[5];
    const float* Wv     = (const float*)d_in[6];
    float* out = (float*)d_out;

    prep_kernel<<<512 + 32 + BT, 128>>>(Wu, Wk, Wv, bu, mask);
    combine_kernel<<<514, 128>>>();
    k2b_kernel<<<256, 128>>>(x);
    attn_kernel<<<2*BT, 256>>>(x, vision);
    k6part_kernel<<<512, 128>>>();
    finish_kernel<<<BT, 256>>>(x, out);
}

// round 8
// speedup vs baseline: 1.1015x; 1.1015x over previous
#include <cuda_runtime.h>
#include <cuda_bf16.h>
#include <math.h>
#include <stdint.h>

#define Bn   4
#define Tn   256
#define Vn   1024
#define Sn   64
#define DIMn 1024
#define CVn  256
#define BT   (Bn*Tn)          // 1024
#define SW   72               // smem word stride (conflict-free fragment LDS)

// ---------------- scratch ----------------
__device__ float g_pp[2][4][CVn*DIMn];     // k1 split-K partials
__device__ float g_Wuk[CVn*DIMn];
__device__ float g_Wuv[CVn*DIMn];
__device__ float g_bias_part[2][16][DIMn];
__device__ float g_buk[DIMn];
__device__ float g_buv[DIMn];
__device__ int   g_idx[BT*Sn];
__device__ float g_Ppart[4][BT*CVn];       // k2b split-K partials
__device__ float g_wp[BT*CVn];             // sum_s e_s * vg_s (with bq factor)
__device__ float g_alpha[BT];              // sum_s e_s (with bq factor)
__device__ float g_opart[2][BT*DIMn];      // k6 split-K partials

// ---------------- bf16 helpers ----------------
__device__ __forceinline__ uint32_t packbf(float x, float y) {
    __nv_bfloat162 h = __floats2bfloat162_rn(x, y);
    return *reinterpret_cast<uint32_t*>(&h);
}
__device__ __forceinline__ void mma_bf16(float c[4], const uint32_t a[4], const uint32_t b[2]) {
    asm volatile("mma.sync.aligned.m16n8k16.row.col.f32.bf16.bf16.f32 "
        "{%0,%1,%2,%3}, {%4,%5,%6,%7}, {%8,%9}, {%0,%1,%2,%3};"
        : "+f"(c[0]), "+f"(c[1]), "+f"(c[2]), "+f"(c[3])
        : "r"(a[0]), "r"(a[1]), "r"(a[2]), "r"(a[3]), "r"(b[0]), "r"(b[1]));
}

// ---------------- bf16 64x64-tile GEMM body, 128 threads ----------------
template<int Nn, int Ks, bool TRANSB>
__device__ __forceinline__ void gemm_bf16(
    const int m0, const int n0, const int k0, const int ksub,
    const float* __restrict__ A, const float* __restrict__ Bm,
    float* __restrict__ C,
    uint32_t Ap[2][8][SW], uint32_t Bp[2][8][SW])
{
    const int tid = threadIdx.x, lane = tid & 31, wid = tid >> 5;
    const int wm = (wid & 1) * 32, wn = (wid >> 1) * 32;
    const int am0 = tid >> 2,         ag0 = tid & 3;
    const int am1 = (tid + 128) >> 2, ag1 = (tid + 128) & 3;
    const int bk2 = tid >> 4,         bng = tid & 15;

    float acc[2][4][4];
    #pragma unroll
    for (int i = 0; i < 2; i++)
        #pragma unroll
        for (int j = 0; j < 4; j++)
            #pragma unroll
            for (int q = 0; q < 4; q++) acc[i][j][q] = 0.f;

    float4 ra0, ra1, rb0, rb1;

    auto loadg = [&](int kt) {
        ra0 = *(const float4*)(A + (size_t)(m0 + am0)*Ks + k0 + kt + ag0*4);
        ra1 = *(const float4*)(A + (size_t)(m0 + am1)*Ks + k0 + kt + ag1*4);
        if (!TRANSB) {
            rb0 = *(const float4*)(Bm + (size_t)(k0 + kt + 2*bk2    )*Nn + n0 + bng*4);
            rb1 = *(const float4*)(Bm + (size_t)(k0 + kt + 2*bk2 + 1)*Nn + n0 + bng*4);
        } else {
            rb0 = *(const float4*)(Bm + (size_t)(n0 + am0)*Ks + k0 + kt + ag0*4);
            rb1 = *(const float4*)(Bm + (size_t)(n0 + am1)*Ks + k0 + kt + ag1*4);
        }
    };
    auto stores = [&](int buf) {
        Ap[buf][ag0*2    ][am0] = packbf(ra0.x, ra0.y);
        Ap[buf][ag0*2 + 1][am0] = packbf(ra0.z, ra0.w);
        Ap[buf][ag1*2    ][am1] = packbf(ra1.x, ra1.y);
        Ap[buf][ag1*2 + 1][am1] = packbf(ra1.z, ra1.w);
        if (!TRANSB) {
            uint4 q;
            q.x = packbf(rb0.x, rb1.x); q.y = packbf(rb0.y, rb1.y);
            q.z = packbf(rb0.z, rb1.z); q.w = packbf(rb0.w, rb1.w);
            *(uint4*)&Bp[buf][bk2][bng*4] = q;
        } else {
            Bp[buf][ag0*2    ][am0] = packbf(rb0.x, rb0.y);
            Bp[buf][ag0*2 + 1][am0] = packbf(rb0.z, rb0.w);
            Bp[buf][ag1*2    ][am1] = packbf(rb1.x, rb1.y);
            Bp[buf][ag1*2 + 1][am1] = packbf(rb1.z, rb1.w);
        }
    };

    loadg(0); stores(0); __syncthreads();
    const int niter = ksub >> 4;
    for (int it = 0; it < niter; it++) {
        const int buf = it & 1;
        const bool nxt = (it + 1 < niter);
        if (nxt) loadg((it + 1) << 4);

        uint32_t af[2][4], bfr[4][2];
        #pragma unroll
        for (int mi = 0; mi < 2; mi++) {
            const int row = wm + mi*16 + (lane >> 2);
            af[mi][0] = Ap[buf][    (lane & 3)][row];
            af[mi][1] = Ap[buf][    (lane & 3)][row + 8];
            af[mi][2] = Ap[buf][4 + (lane & 3)][row];
            af[mi][3] = Ap[buf][4 + (lane & 3)][row + 8];
        }
        #pragma unroll
        for (int ni = 0; ni < 4; ni++) {
            const int col = wn + ni*8 + (lane >> 2);
            bfr[ni][0] = Bp[buf][    (lane & 3)][col];
            bfr[ni][1] = Bp[buf][4 + (lane & 3)][col];
        }
        #pragma unroll
        for (int mi = 0; mi < 2; mi++)
            #pragma unroll
            for (int ni = 0; ni < 4; ni++)
                mma_bf16(acc[mi][ni], af[mi], bfr[ni]);

        if (nxt) { stores(buf ^ 1); __syncthreads(); }
    }

    #pragma unroll
    for (int mi = 0; mi < 2; mi++) {
        const int r = m0 + wm + mi*16 + (lane >> 2);
        #pragma unroll
        for (int ni = 0; ni < 4; ni++) {
            const int c = n0 + wn + ni*8 + 2*(lane & 3);
            float2 o0, o1;
            o0.x = acc[mi][ni][0]; o0.y = acc[mi][ni][1];
            o1.x = acc[mi][ni][2]; o1.y = acc[mi][ni][3];
            *(float2*)(C + (size_t)r*Nn + c) = o0;
            *(float2*)(C + (size_t)(r + 8)*Nn + c) = o1;
        }
    }
}

// ---------------- prep: k1 partials (512) + bias partials (32) + build_idx (1024) ----------------
__global__ void __launch_bounds__(128)
prep_kernel(const float* __restrict__ Wu, const float* __restrict__ Wk,
            const float* __restrict__ Wv, const float* __restrict__ bu,
            const void* __restrict__ maskp) {
    __shared__ __align__(16) uint32_t Ap[2][8][SW];
    __shared__ __align__(16) uint32_t Bp[2][8][SW];
    const int bid = blockIdx.x;
    const int tid = threadIdx.x;

    if (bid < 512) {
        const int z = bid >> 8, r = bid & 255;
        const int ks = r >> 6, t = r & 63;
        const int m0 = (t >> 4) * 64, n0 = (t & 15) * 64;
        gemm_bf16<DIMn, DIMn, false>(m0, n0, ks*256, 256, Wu,
                                     z ? Wv : Wk, g_pp[z][ks], Ap, Bp);
    } else if (bid < 544) {
        const int r = bid - 512;
        const int z = r & 1, slice = r >> 1;
        const float* W = z ? Wv : Wk;
        const int d0 = slice * 64;
        __shared__ float sbu[64];
        if (tid < 64) sbu[tid] = bu[d0 + tid];
        __syncthreads();
        float acc[8];
        #pragma unroll
        for (int k = 0; k < 8; k++) acc[k] = 0.f;
        for (int dd = 0; dd < 64; dd++) {
            const float bv = sbu[dd];
            const float* row = W + (size_t)(d0 + dd)*DIMn + tid;
            #pragma unroll
            for (int k = 0; k < 8; k++) acc[k] += bv * row[128*k];
        }
        #pragma unroll
        for (int k = 0; k < 8; k++) g_bias_part[z][slice][tid + 128*k] = acc[k];
    } else {
        const int bt = bid - 544, b = bt >> 8, t = bt & 255;
        const int lane = tid & 31, wid = tid >> 5;
        const unsigned char* m8 = (const unsigned char*)maskp;
        const int* m32 = (const int*)maskp;

        int dsum = 0;
        #pragma unroll
        for (int u = 0; u < 8; u++) dsum += (m8[(tid*8 + u)*4 + 1] != 0);
        const bool u8 = (__syncthreads_or(dsum) != 0);

        int flags = 0, cnt = 0;
        #pragma unroll
        for (int u = 0; u < 8; u++) {
            const int v = tid*8 + u;
            const int e = (b*Vn + v)*Tn + t;
            const int mm = u8 ? (int)m8[e] : (m32[e] != 0);
            if (mm) { flags |= (1 << u); cnt++; }
        }
        int val = cnt;
        #pragma unroll
        for (int off = 1; off < 32; off <<= 1) {
            int vv = __shfl_up_sync(0xffffffffu, val, off);
            if (lane >= off) val += vv;
        }
        __shared__ int wtot[4];
        if (lane == 31) wtot[wid] = val;
        __syncthreads();
        int woff = 0, total = 0;
        #pragma unroll
        for (int w = 0; w < 4; w++) { int tw = wtot[w]; if (w < wid) woff += tw; total += tw; }
        int pos = woff + val - cnt;
        #pragma unroll
        for (int u = 0; u < 8; u++)
            if (flags & (1 << u)) { if (pos < Sn) g_idx[bt*Sn + pos] = tid*8 + u; pos++; }
        if (tid == 0)
            for (int p = total; p < Sn; p++) g_idx[bt*Sn + p] = Vn;
    }
}

// ---------------- combine: Wuk/Wuv (512) + buk/buv (2) ----------------
__global__ void __launch_bounds__(128)
combine_kernel() {
    const int bid = blockIdx.x, tid = threadIdx.x;
    if (bid < 512) {
        #pragma unroll
        for (int h = 0; h < 2; h++) {
            const int F = bid*256 + h*128 + tid;
            const int z = F >> 16, off4 = F & 65535;
            float4 s = make_float4(0.f, 0.f, 0.f, 0.f);
            #pragma unroll
            for (int p = 0; p < 4; p++) {
                float4 v = ((const float4*)g_pp[z][p])[off4];
                s.x += v.x; s.y += v.y; s.z += v.z; s.w += v.w;
            }
            ((float4*)(z ? g_Wuv : g_Wuk))[off4] = s;
        }
    } else {
        const int z = bid - 512;
        #pragma unroll
        for (int h = 0; h < 8; h++) {
            const int j = h*128 + tid;
            float a = 0.f;
            #pragma unroll
            for (int p = 0; p < 16; p++) a += g_bias_part[z][p][j];
            (z ? g_buv : g_buk)[j] = a;
        }
    }
}

// ---------------- k2b: P partials, split-K x4 (256 blocks) ----------------
__global__ void __launch_bounds__(128)
k2b_kernel(const float* __restrict__ x) {
    __shared__ __align__(16) uint32_t Ap[2][8][SW];
    __shared__ __align__(16) uint32_t Bp[2][8][SW];
    const int bid = blockIdx.x;
    const int ks = bid >> 6, r = bid & 63;
    const int m0 = (r >> 2) * 64, n0 = (r & 3) * 64;
    gemm_bf16<CVn, DIMn, true>(m0, n0, ks*256, 256, x, g_Wuk, g_Ppart[ks], Ap, Bp);
}

// ---------------- attn: one CTA per (b,t); warp-per-row gather+dot, bf16 staging ----------------
__global__ void __launch_bounds__(256)
attn_kernel(const float* __restrict__ x, const float* __restrict__ vision) {
    __shared__ uint32_t vg16[Sn][128];     // bf16x2 pairs, 32 KB
    __shared__ float e_s[Sn];
    __shared__ int   idx_s[Sn];
    __shared__ float red_s[8];
    __shared__ float2 part_s[128];

    const int bt = blockIdx.x, b = bt >> 8, tid = threadIdx.x;
    const int lane = tid & 31, wid = tid >> 5;

    if (tid < Sn) idx_s[tid] = g_idx[bt*Sn + tid];

    // bq partials (off critical path; applied as exp-factor at the end)
    {
        float4 xv = *(const float4*)(x + (size_t)bt*DIMn + tid*4);
        float4 bv = *(const float4*)(g_buk + tid*4);
        float a = xv.x*bv.x + xv.y*bv.y + xv.z*bv.z + xv.w*bv.w;
        #pragma unroll
        for (int off = 16; off; off >>= 1) a += __shfl_down_sync(0xffffffffu, a, off);
        if (lane == 0) red_s[wid] = a;
    }

    // P in registers: lane owns cols 4l..4l+3 and 128+4l..128+4l+3 (4-way partial combine)
    float4 Pa, Pb;
    {
        const float4* p0 = (const float4*)(g_Ppart[0] + bt*CVn);
        const float4* p1 = (const float4*)(g_Ppart[1] + bt*CVn);
        const float4* p2 = (const float4*)(g_Ppart[2] + bt*CVn);
        const float4* p3 = (const float4*)(g_Ppart[3] + bt*CVn);
        float4 a0 = p0[lane], a1 = p1[lane], a2 = p2[lane], a3 = p3[lane];
        Pa.x = a0.x + a1.x + a2.x + a3.x; Pa.y = a0.y + a1.y + a2.y + a3.y;
        Pa.z = a0.z + a1.z + a2.z + a3.z; Pa.w = a0.w + a1.w + a2.w + a3.w;
        a0 = p0[lane+32]; a1 = p1[lane+32]; a2 = p2[lane+32]; a3 = p3[lane+32];
        Pb.x = a0.x + a1.x + a2.x + a3.x; Pb.y = a0.y + a1.y + a2.y + a3.y;
        Pb.z = a0.z + a1.z + a2.z + a3.z; Pb.w = a0.w + a1.w + a2.w + a3.w;
    }
    __syncthreads();   // idx_s + red_s ready

    // gather + dot: warp w owns row 8*pass + w
    #pragma unroll
    for (int pass = 0; pass < 8; pass++) {
        const int r = pass*8 + wid;
        const int idx = idx_s[r];
        float4 va = make_float4(0.f,0.f,0.f,0.f), vb = va;
        if (idx < Vn) {
            const float4* vr = (const float4*)(vision + ((size_t)(b*Vn + idx))*CVn);
            va = vr[lane]; vb = vr[lane + 32];
        }
        uint2 qa, qb;
        qa.x = packbf(va.x, va.y); qa.y = packbf(va.z, va.w);
        qb.x = packbf(vb.x, vb.y); qb.y = packbf(vb.z, vb.w);
        *(uint2*)&vg16[r][2*lane]      = qa;
        *(uint2*)&vg16[r][64 + 2*lane] = qb;
        float d = va.x*Pa.x + va.y*Pa.y + va.z*Pa.z + va.w*Pa.w
                + vb.x*Pb.x + vb.y*Pb.y + vb.z*Pb.z + vb.w*Pb.w;
        #pragma unroll
        for (int off = 16; off; off >>= 1) d += __shfl_down_sync(0xffffffffu, d, off);
        if (lane == 0) {
            float lp = d * 0.03125f + (idx < Vn ? 0.f : 100.f);
            e_s[r] = __expf(fminf(lp, 80.f));
        }
    }
    __syncthreads();

    const float bqv = red_s[0] + red_s[1] + red_s[2] + red_s[3]
                    + red_s[4] + red_s[5] + red_s[6] + red_s[7];
    const float f = __expf(bqv * 0.03125f);

    // wsum: thread handles bf16x2 pair c = tid&127, s-half = tid>>7
    {
        const int c = tid & 127, sh = tid >> 7, s0 = sh * 32;
        float ax = 0.f, ay = 0.f;
        #pragma unroll 8
        for (int s = 0; s < 32; s++) {
            const float e = e_s[s0 + s];
            const uint32_t u = vg16[s0 + s][c];
            __nv_bfloat162 h = *reinterpret_cast<const __nv_bfloat162*>(&u);
            float2 vv = __bfloat1622float2(h);
            ax += e * vv.x; ay += e * vv.y;
        }
        if (sh == 1) { part_s[c].x = ax; part_s[c].y = ay; }
        __syncthreads();
        if (sh == 0) {
            float2 o;
            o.x = (ax + part_s[c].x) * f;
            o.y = (ay + part_s[c].y) * f;
            *(float2*)(g_wp + bt*CVn + 2*c) = o;
        }
    }

    if (tid < 32) {
        float a = e_s[tid] + e_s[tid + 32];
        #pragma unroll
        for (int off = 16; off; off >>= 1) a += __shfl_down_sync(0xffffffffu, a, off);
        if (tid == 0) g_alpha[bt] = a * f;
    }
}

// ---------------- k6part: out-GEMM partials split-K x2 (512) ----------------
__global__ void __launch_bounds__(128)
k6part_kernel() {
    __shared__ __align__(16) uint32_t Ap[2][8][SW];
    __shared__ __align__(16) uint32_t Bp[2][8][SW];
    const int bid = blockIdx.x;
    const int ks = bid >> 8, r = bid & 255;
    const int m0 = (r >> 4) * 64, n0 = (r & 15) * 64;
    gemm_bf16<DIMn, CVn, false>(m0, n0, ks*128, 128, g_wp, g_Wuv, g_opart[ks], Ap, Bp);
}

// ---------------- finish: out = (p0+p1 + alpha*buv)/Z_b + x ----------------
__global__ void __launch_bounds__(256)
finish_kernel(const float* __restrict__ x, float* __restrict__ out) {
    const int r = blockIdx.x, b = r >> 8, tid = threadIdx.x;
    const int lane = tid & 31, wid = tid >> 5;
    __shared__ float zr[8];

    float a = g_alpha[b*256 + tid];
    #pragma unroll
    for (int off = 16; off; off >>= 1) a += __shfl_down_sync(0xffffffffu, a, off);
    if (lane == 0) zr[wid] = a;
    __syncthreads();
    const float Z = zr[0] + zr[1] + zr[2] + zr[3] + zr[4] + zr[5] + zr[6] + zr[7];
    const float iz = 1.0f / Z;

    const float al = g_alpha[r];
    float4 p0 = ((const float4*)g_opart[0])[r*256 + tid];
    float4 p1 = ((const float4*)g_opart[1])[r*256 + tid];
    float4 bv = ((const float4*)g_buv)[tid];
    float4 xv = ((const float4*)x)[r*256 + tid];
    float4 o;
    o.x = (p0.x + p1.x + al*bv.x)*iz + xv.x;
    o.y = (p0.y + p1.y + al*bv.y)*iz + xv.y;
    o.z = (p0.z + p1.z + al*bv.z)*iz + xv.z;
    o.w = (p0.w + p1.w + al*bv.w)*iz + xv.w;
    ((float4*)out)[r*256 + tid] = o;
}

// ---------------- launch ----------------
extern "C" void kernel_launch(void* const* d_in, const int* in_sizes, int n_in,
                              void* d_out, int out_size) {
    const float* x      = (const float*)d_in[0];
    const float* vision = (const float*)d_in[1];
    const void*  mask   = d_in[2];
    const float* Wu     = (const float*)d_in[3];
    const float* bu     = (const float*)d_in[4];
    const float* Wk     = (const float*)d_in[5];
    const float* Wv     = (const float*)d_in[6];
    float* out = (float*)d_out;

    prep_kernel<<<512 + 32 + BT, 128>>>(Wu, Wk, Wv, bu, mask);
    combine_kernel<<<514, 128>>>();
    k2b_kernel<<<256, 128>>>(x);
    attn_kernel<<<BT, 256>>>(x, vision);
    k6part_kernel<<<512, 128>>>();
    finish_kernel<<<BT, 256>>>(x, out);
}

// round 9
// speedup vs baseline: 1.1723x; 1.0642x over previous
#include <cuda_runtime.h>
#include <cuda_bf16.h>
#include <math.h>
#include <stdint.h>

#define Bn   4
#define Tn   256
#define Vn   1024
#define Sn   64
#define DIMn 1024
#define CVn  256
#define BT   (Bn*Tn)          // 1024
#define SW   72               // smem word stride (conflict-free fragment LDS)

// ---------------- scratch ----------------
__device__ float    g_pp[2][4][CVn*DIMn];     // k1 split-K partials
__device__ uint32_t g_Wuk16[CVn*DIMn/2];      // bf16x2
__device__ uint32_t g_Wuv16[CVn*DIMn/2];
__device__ float    g_bias_part[2][16][DIMn];
__device__ float    g_buk[DIMn];
__device__ float    g_buv[DIMn];
__device__ int      g_idx[BT*Sn];
__device__ float    g_Ppart[4][BT*CVn];       // k2b split-K partials (fp32)
__device__ uint32_t g_vis16[Bn*Vn*CVn/2];     // bf16x2 vision
__device__ uint32_t g_x16[BT*DIMn/2];         // bf16x2 x
__device__ uint32_t g_wp16[BT*CVn/2];         // bf16x2 wp
__device__ float    g_alpha[BT];
__device__ float    g_opart[2][BT*DIMn];      // k6 split-K partials

// ---------------- bf16 helpers ----------------
__device__ __forceinline__ uint32_t packbf(float x, float y) {
    __nv_bfloat162 h = __floats2bfloat162_rn(x, y);
    return *reinterpret_cast<uint32_t*>(&h);
}
__device__ __forceinline__ float2 unpackbf(uint32_t u) {
    return __bfloat1622float2(*reinterpret_cast<const __nv_bfloat162*>(&u));
}
__device__ __forceinline__ void mma_bf16(float c[4], const uint32_t a[4], const uint32_t b[2]) {
    asm volatile("mma.sync.aligned.m16n8k16.row.col.f32.bf16.bf16.f32 "
        "{%0,%1,%2,%3}, {%4,%5,%6,%7}, {%8,%9}, {%0,%1,%2,%3};"
        : "+f"(c[0]), "+f"(c[1]), "+f"(c[2]), "+f"(c[3])
        : "r"(a[0]), "r"(a[1]), "r"(a[2]), "r"(a[3]), "r"(b[0]), "r"(b[1]));
}

// ---------------- shared mainloop + epilogue ----------------
__device__ __forceinline__ void mma_tile_loop(
    int buf, int wm, int wn, int lane,
    uint32_t Ap[2][8][SW], uint32_t Bp[2][8][SW], float acc[2][4][4])
{
    uint32_t af[2][4], bfr[4][2];
    #pragma unroll
    for (int mi = 0; mi < 2; mi++) {
        const int row = wm + mi*16 + (lane >> 2);
        af[mi][0] = Ap[buf][    (lane & 3)][row];
        af[mi][1] = Ap[buf][    (lane & 3)][row + 8];
        af[mi][2] = Ap[buf][4 + (lane & 3)][row];
        af[mi][3] = Ap[buf][4 + (lane & 3)][row + 8];
    }
    #pragma unroll
    for (int ni = 0; ni < 4; ni++) {
        const int col = wn + ni*8 + (lane >> 2);
        bfr[ni][0] = Bp[buf][    (lane & 3)][col];
        bfr[ni][1] = Bp[buf][4 + (lane & 3)][col];
    }
    #pragma unroll
    for (int mi = 0; mi < 2; mi++)
        #pragma unroll
        for (int ni = 0; ni < 4; ni++)
            mma_bf16(acc[mi][ni], af[mi], bfr[ni]);
}

template<int Nn>
__device__ __forceinline__ void epi_store(
    int m0, int n0, int wm, int wn, int lane,
    float acc[2][4][4], float* __restrict__ C)
{
    #pragma unroll
    for (int mi = 0; mi < 2; mi++) {
        const int r = m0 + wm + mi*16 + (lane >> 2);
        #pragma unroll
        for (int ni = 0; ni < 4; ni++) {
            const int c = n0 + wn + ni*8 + 2*(lane & 3);
            float2 o0, o1;
            o0.x = acc[mi][ni][0]; o0.y = acc[mi][ni][1];
            o1.x = acc[mi][ni][2]; o1.y = acc[mi][ni][3];
            *(float2*)(C + (size_t)r*Nn + c) = o0;
            *(float2*)(C + (size_t)(r + 8)*Nn + c) = o1;
        }
    }
}

// ---------------- fp32-operand GEMM (k1 only), 128 threads, 64x64 tile ----------------
template<int Nn, int Ks>
__device__ __forceinline__ void gemm_f32(
    const int m0, const int n0, const int k0, const int ksub,
    const float* __restrict__ A, const float* __restrict__ Bm,
    float* __restrict__ C,
    uint32_t Ap[2][8][SW], uint32_t Bp[2][8][SW])
{
    const int tid = threadIdx.x, lane = tid & 31, wid = tid >> 5;
    const int wm = (wid & 1) * 32, wn = (wid >> 1) * 32;
    const int am0 = tid >> 2,         ag0 = tid & 3;
    const int am1 = (tid + 128) >> 2, ag1 = (tid + 128) & 3;
    const int bk2 = tid >> 4,         bng = tid & 15;

    float acc[2][4][4];
    #pragma unroll
    for (int i = 0; i < 2; i++)
        #pragma unroll
        for (int j = 0; j < 4; j++)
            #pragma unroll
            for (int q = 0; q < 4; q++) acc[i][j][q] = 0.f;

    float4 ra0, ra1, rb0, rb1;
    auto loadg = [&](int kt) {
        ra0 = *(const float4*)(A + (size_t)(m0 + am0)*Ks + k0 + kt + ag0*4);
        ra1 = *(const float4*)(A + (size_t)(m0 + am1)*Ks + k0 + kt + ag1*4);
        rb0 = *(const float4*)(Bm + (size_t)(k0 + kt + 2*bk2    )*Nn + n0 + bng*4);
        rb1 = *(const float4*)(Bm + (size_t)(k0 + kt + 2*bk2 + 1)*Nn + n0 + bng*4);
    };
    auto stores = [&](int buf) {
        Ap[buf][ag0*2    ][am0] = packbf(ra0.x, ra0.y);
        Ap[buf][ag0*2 + 1][am0] = packbf(ra0.z, ra0.w);
        Ap[buf][ag1*2    ][am1] = packbf(ra1.x, ra1.y);
        Ap[buf][ag1*2 + 1][am1] = packbf(ra1.z, ra1.w);
        uint4 q;
        q.x = packbf(rb0.x, rb1.x); q.y = packbf(rb0.y, rb1.y);
        q.z = packbf(rb0.z, rb1.z); q.w = packbf(rb0.w, rb1.w);
        *(uint4*)&Bp[buf][bk2][bng*4] = q;
    };

    loadg(0); stores(0); __syncthreads();
    const int niter = ksub >> 4;
    for (int it = 0; it < niter; it++) {
        const int buf = it & 1;
        const bool nxt = (it + 1 < niter);
        if (nxt) loadg((it + 1) << 4);
        mma_tile_loop(buf, wm, wn, lane, Ap, Bp, acc);
        if (nxt) { stores(buf ^ 1); __syncthreads(); }
    }
    epi_store<Nn>(m0, n0, wm, wn, lane, acc, C);
}

// ---------------- bf16-operand GEMM (k2b, k6part), 128 threads, 64x64 tile ----------------
// A: bf16 [M,Ks] row-major (as uint32 pairs). B: bf16 [K,Nn] row-major (TRANSB=0)
// or [N,Ks] row-major (TRANSB=1).
template<int Nn, int Ks, bool TRANSB>
__device__ __forceinline__ void gemm_1616(
    const int m0, const int n0, const int k0, const int ksub,
    const uint32_t* __restrict__ A16, const uint32_t* __restrict__ B16,
    float* __restrict__ C,
    uint32_t Ap[2][8][SW], uint32_t Bp[2][8][SW])
{
    const int tid = threadIdx.x, lane = tid & 31, wid = tid >> 5;
    const int wm = (wid & 1) * 32, wn = (wid >> 1) * 32;
    const int am = tid >> 1, akg = tid & 1;       // A: row, 8-k group
    const int bk2 = tid >> 4, bn4 = (tid & 15) * 4;  // B no-trans

    float acc[2][4][4];
    #pragma unroll
    for (int i = 0; i < 2; i++)
        #pragma unroll
        for (int j = 0; j < 4; j++)
            #pragma unroll
            for (int q = 0; q < 4; q++) acc[i][j][q] = 0.f;

    uint4 qa; uint2 rb0, rb1; uint4 qb;

    auto loadg = [&](int kt) {
        // A: uint4 = 8 bf16 = k-span 8 (word index = elem/2)
        qa = *(const uint4*)(A16 + (size_t)(m0 + am)*(Ks/2) + (k0 + kt)/2 + akg*4);
        if (!TRANSB) {
            rb0 = *(const uint2*)(B16 + (size_t)(k0 + kt + 2*bk2    )*(Nn/2) + (n0 + bn4)/2);
            rb1 = *(const uint2*)(B16 + (size_t)(k0 + kt + 2*bk2 + 1)*(Nn/2) + (n0 + bn4)/2);
        } else {
            qb = *(const uint4*)(B16 + (size_t)(n0 + am)*(Ks/2) + (k0 + kt)/2 + akg*4);
        }
    };
    auto stores = [&](int buf) {
        Ap[buf][akg*4 + 0][am] = qa.x;
        Ap[buf][akg*4 + 1][am] = qa.y;
        Ap[buf][akg*4 + 2][am] = qa.z;
        Ap[buf][akg*4 + 3][am] = qa.w;
        if (!TRANSB) {
            uint4 q;
            q.x = __byte_perm(rb0.x, rb1.x, 0x5410);
            q.y = __byte_perm(rb0.x, rb1.x, 0x7632);
            q.z = __byte_perm(rb0.y, rb1.y, 0x5410);
            q.w = __byte_perm(rb0.y, rb1.y, 0x7632);
            *(uint4*)&Bp[buf][bk2][bn4] = q;
        } else {
            Bp[buf][akg*4 + 0][am] = qb.x;
            Bp[buf][akg*4 + 1][am] = qb.y;
            Bp[buf][akg*4 + 2][am] = qb.z;
            Bp[buf][akg*4 + 3][am] = qb.w;
        }
    };

    loadg(0); stores(0); __syncthreads();
    const int niter = ksub >> 4;
    for (int it = 0; it < niter; it++) {
        const int buf = it & 1;
        const bool nxt = (it + 1 < niter);
        if (nxt) loadg((it + 1) << 4);
        mma_tile_loop(buf, wm, wn, lane, Ap, Bp, acc);
        if (nxt) { stores(buf ^ 1); __syncthreads(); }
    }
    epi_store<Nn>(m0, n0, wm, wn, lane, acc, C);
}

// ---------------- prep: k1 partials (512) + bias (32) + idx (1024) + converts (128) ----------------
__global__ void __launch_bounds__(128)
prep_kernel(const float* __restrict__ Wu, const float* __restrict__ Wk,
            const float* __restrict__ Wv, const float* __restrict__ bu,
            const void* __restrict__ maskp,
            const float* __restrict__ x, const float* __restrict__ vision) {
    __shared__ __align__(16) uint32_t Ap[2][8][SW];
    __shared__ __align__(16) uint32_t Bp[2][8][SW];
    const int bid = blockIdx.x;
    const int tid = threadIdx.x;

    if (bid < 512) {
        const int z = bid >> 8, r = bid & 255;
        const int ks = r >> 6, t = r & 63;
        const int m0 = (t >> 4) * 64, n0 = (t & 15) * 64;
        gemm_f32<DIMn, DIMn>(m0, n0, ks*256, 256, Wu, z ? Wv : Wk,
                             g_pp[z][ks], Ap, Bp);
    } else if (bid < 544) {
        const int r = bid - 512;
        const int z = r & 1, slice = r >> 1;
        const float* W = z ? Wv : Wk;
        const int d0 = slice * 64;
        __shared__ float sbu[64];
        if (tid < 64) sbu[tid] = bu[d0 + tid];
        __syncthreads();
        float acc[8];
        #pragma unroll
        for (int k = 0; k < 8; k++) acc[k] = 0.f;
        for (int dd = 0; dd < 64; dd++) {
            const float bv = sbu[dd];
            const float* row = W + (size_t)(d0 + dd)*DIMn + tid;
            #pragma unroll
            for (int k = 0; k < 8; k++) acc[k] += bv * row[128*k];
        }
        #pragma unroll
        for (int k = 0; k < 8; k++) g_bias_part[z][slice][tid + 128*k] = acc[k];
    } else if (bid < 1568) {
        const int bt = bid - 544, b = bt >> 8, t = bt & 255;
        const int lane = tid & 31, wid = tid >> 5;
        const unsigned char* m8 = (const unsigned char*)maskp;
        const int* m32 = (const int*)maskp;

        int dsum = 0;
        #pragma unroll
        for (int u = 0; u < 8; u++) dsum += (m8[(tid*8 + u)*4 + 1] != 0);
        const bool u8 = (__syncthreads_or(dsum) != 0);

        int flags = 0, cnt = 0;
        #pragma unroll
        for (int u = 0; u < 8; u++) {
            const int v = tid*8 + u;
            const int e = (b*Vn + v)*Tn + t;
            const int mm = u8 ? (int)m8[e] : (m32[e] != 0);
            if (mm) { flags |= (1 << u); cnt++; }
        }
        int val = cnt;
        #pragma unroll
        for (int off = 1; off < 32; off <<= 1) {
            int vv = __shfl_up_sync(0xffffffffu, val, off);
            if (lane >= off) val += vv;
        }
        __shared__ int wtot[4];
        if (lane == 31) wtot[wid] = val;
        __syncthreads();
        int woff = 0, total = 0;
        #pragma unroll
        for (int w = 0; w < 4; w++) { int tw = wtot[w]; if (w < wid) woff += tw; total += tw; }
        int pos = woff + val - cnt;
        #pragma unroll
        for (int u = 0; u < 8; u++)
            if (flags & (1 << u)) { if (pos < Sn) g_idx[bt*Sn + pos] = tid*8 + u; pos++; }
        if (tid == 0)
            for (int p = total; p < Sn; p++) g_idx[bt*Sn + p] = Vn;
    } else {
        // bf16 converts: 64 blocks vision, 64 blocks x (each 512K words total)
        const int r = bid - 1568;
        const bool isv = (r < 64);
        const int j = isv ? r : r - 64;
        const float2* src = (const float2*)(isv ? vision : x);
        uint32_t* dst = isv ? g_vis16 : g_x16;
        #pragma unroll
        for (int i = 0; i < 64; i++) {
            const int w = j*8192 + i*128 + tid;
            float2 v = src[w];
            dst[w] = packbf(v.x, v.y);
        }
    }
}

// ---------------- combine: Wuk16/Wuv16 (512) + buk/buv (2) ----------------
__global__ void __launch_bounds__(128)
combine_kernel() {
    const int bid = blockIdx.x, tid = threadIdx.x;
    if (bid < 512) {
        #pragma unroll
        for (int h = 0; h < 2; h++) {
            const int F = bid*256 + h*128 + tid;
            const int z = F >> 16, off4 = F & 65535;
            float4 s = make_float4(0.f, 0.f, 0.f, 0.f);
            #pragma unroll
            for (int p = 0; p < 4; p++) {
                float4 v = ((const float4*)g_pp[z][p])[off4];
                s.x += v.x; s.y += v.y; s.z += v.z; s.w += v.w;
            }
            uint2 o; o.x = packbf(s.x, s.y); o.y = packbf(s.z, s.w);
            ((uint2*)(z ? g_Wuv16 : g_Wuk16))[off4] = o;
        }
    } else {
        const int z = bid - 512;
        #pragma unroll
        for (int h = 0; h < 8; h++) {
            const int j = h*128 + tid;
            float a = 0.f;
            #pragma unroll
            for (int p = 0; p < 16; p++) a += g_bias_part[z][p][j];
            (z ? g_buv : g_buk)[j] = a;
        }
    }
}

// ---------------- k2b: P partials, split-K x4 (256 blocks), bf16 operands ----------------
__global__ void __launch_bounds__(128)
k2b_kernel() {
    __shared__ __align__(16) uint32_t Ap[2][8][SW];
    __shared__ __align__(16) uint32_t Bp[2][8][SW];
    const int bid = blockIdx.x;
    const int ks = bid >> 6, r = bid & 63;
    const int m0 = (r >> 2) * 64, n0 = (r & 3) * 64;
    gemm_1616<CVn, DIMn, true>(m0, n0, ks*256, 256, g_x16, g_Wuk16,
                               g_Ppart[ks], Ap, Bp);
}

// ---------------- attn: warp-per-row bf16 gather+dot ----------------
__global__ void __launch_bounds__(256)
attn_kernel(const float* __restrict__ x) {
    __shared__ uint32_t vg16[Sn][128];     // bf16x2, 32 KB
    __shared__ float e_s[Sn];
    __shared__ int   idx_s[Sn];
    __shared__ float red_s[8];
    __shared__ float2 part_s[128];

    const int bt = blockIdx.x, b = bt >> 8, tid = threadIdx.x;
    const int lane = tid & 31, wid = tid >> 5;

    if (tid < Sn) idx_s[tid] = g_idx[bt*Sn + tid];

    // bq partials
    {
        float4 xv = *(const float4*)(x + (size_t)bt*DIMn + tid*4);
        float4 bv = *(const float4*)(g_buk + tid*4);
        float a = xv.x*bv.x + xv.y*bv.y + xv.z*bv.z + xv.w*bv.w;
        #pragma unroll
        for (int off = 16; off; off >>= 1) a += __shfl_down_sync(0xffffffffu, a, off);
        if (lane == 0) red_s[wid] = a;
    }

    // P in registers: lane owns cols 8l..8l+7 (4-way partial combine)
    float Pr[8];
    {
        #pragma unroll
        for (int i = 0; i < 8; i++) Pr[i] = 0.f;
        #pragma unroll
        for (int p = 0; p < 4; p++) {
            const float4* pp = (const float4*)(g_Ppart[p] + bt*CVn);
            float4 a0 = pp[2*lane], a1 = pp[2*lane + 1];
            Pr[0] += a0.x; Pr[1] += a0.y; Pr[2] += a0.z; Pr[3] += a0.w;
            Pr[4] += a1.x; Pr[5] += a1.y; Pr[6] += a1.z; Pr[7] += a1.w;
        }
    }
    __syncthreads();

    // gather + dot: warp w owns row 8*pass + w; one uint4 (8 bf16) per lane
    #pragma unroll
    for (int pass = 0; pass < 8; pass++) {
        const int r = pass*8 + wid;
        const int idx = idx_s[r];
        uint4 q = make_uint4(0u, 0u, 0u, 0u);
        if (idx < Vn)
            q = ((const uint4*)(g_vis16 + (size_t)(b*Vn + idx)*128))[lane];
        ((uint4*)&vg16[r][0])[lane] = q;
        float2 v0 = unpackbf(q.x), v1 = unpackbf(q.y);
        float2 v2 = unpackbf(q.z), v3 = unpackbf(q.w);
        float d = v0.x*Pr[0] + v0.y*Pr[1] + v1.x*Pr[2] + v1.y*Pr[3]
                + v2.x*Pr[4] + v2.y*Pr[5] + v3.x*Pr[6] + v3.y*Pr[7];
        #pragma unroll
        for (int off = 16; off; off >>= 1) d += __shfl_down_sync(0xffffffffu, d, off);
        if (lane == 0) {
            float lp = d * 0.03125f + (idx < Vn ? 0.f : 100.f);
            e_s[r] = __expf(fminf(lp, 80.f));
        }
    }
    __syncthreads();

    const float bqv = red_s[0] + red_s[1] + red_s[2] + red_s[3]
                    + red_s[4] + red_s[5] + red_s[6] + red_s[7];
    const float f = __expf(bqv * 0.03125f);

    // wsum: thread handles bf16x2 pair c = tid&127, s-half = tid>>7
    {
        const int c = tid & 127, sh = tid >> 7, s0 = sh * 32;
        float ax = 0.f, ay = 0.f;
        #pragma unroll 8
        for (int s = 0; s < 32; s++) {
            const float e = e_s[s0 + s];
            float2 vv = unpackbf(vg16[s0 + s][c]);
            ax += e * vv.x; ay += e * vv.y;
        }
        if (sh == 1) { part_s[c].x = ax; part_s[c].y = ay; }
        __syncthreads();
        if (sh == 0)
            g_wp16[bt*128 + c] = packbf((ax + part_s[c].x) * f,
                                        (ay + part_s[c].y) * f);
    }

    if (tid < 32) {
        float a = e_s[tid] + e_s[tid + 32];
        #pragma unroll
        for (int off = 16; off; off >>= 1) a += __shfl_down_sync(0xffffffffu, a, off);
        if (tid == 0) g_alpha[bt] = a * f;
    }
}

// ---------------- k6part: out-GEMM partials split-K x2 (512), bf16 operands ----------------
__global__ void __launch_bounds__(128)
k6part_kernel() {
    __shared__ __align__(16) uint32_t Ap[2][8][SW];
    __shared__ __align__(16) uint32_t Bp[2][8][SW];
    const int bid = blockIdx.x;
    const int ks = bid >> 8, r = bid & 255;
    const int m0 = (r >> 4) * 64, n0 = (r & 15) * 64;
    gemm_1616<DIMn, CVn, false>(m0, n0, ks*128, 128, g_wp16, g_Wuv16,
                                g_opart[ks], Ap, Bp);
}

// ---------------- finish: out = (p0+p1 + alpha*buv)/Z_b + x ----------------
__global__ void __launch_bounds__(256)
finish_kernel(const float* __restrict__ x, float* __restrict__ out) {
    const int r = blockIdx.x, b = r >> 8, tid = threadIdx.x;
    const int lane = tid & 31, wid = tid >> 5;
    __shared__ float zr[8];

    float a = g_alpha[b*256 + tid];
    #pragma unroll
    for (int off = 16; off; off >>= 1) a += __shfl_down_sync(0xffffffffu, a, off);
    if (lane == 0) zr[wid] = a;
    __syncthreads();
    const float Z = zr[0] + zr[1] + zr[2] + zr[3] + zr[4] + zr[5] + zr[6] + zr[7];
    const float iz = 1.0f / Z;

    const float al = g_alpha[r];
    float4 p0 = ((const float4*)g_opart[0])[r*256 + tid];
    float4 p1 = ((const float4*)g_opart[1])[r*256 + tid];
    float4 bv = ((const float4*)g_buv)[tid];
    float4 xv = ((const float4*)x)[r*256 + tid];
    float4 o;
    o.x = (p0.x + p1.x + al*bv.x)*iz + xv.x;
    o.y = (p0.y + p1.y + al*bv.y)*iz + xv.y;
    o.z = (p0.z + p1.z + al*bv.z)*iz + xv.z;
    o.w = (p0.w + p1.w + al*bv.w)*iz + xv.w;
    ((float4*)out)[r*256 + tid] = o;
}

// ---------------- launch ----------------
extern "C" void kernel_launch(void* const* d_in, const int* in_sizes, int n_in,
                              void* d_out, int out_size) {
    const float* x      = (const float*)d_in[0];
    const float* vision = (const float*)d_in[1];
    const void*  mask   = d_in[2];
    const float* Wu     = (const float*)d_in[3];
    const float* bu     = (const float*)d_in[4];
    const float* Wk     = (const float*)d_in[5];
    const float* Wv     = (const float*)d_in[6];
    float* out = (float*)d_out;

    prep_kernel<<<1568 + 128, 128>>>(Wu, Wk, Wv, bu, mask, x, vision);
    combine_kernel<<<514, 128>>>();
    k2b_kernel<<<256, 128>>>();
    attn_kernel<<<BT, 256>>>(x);
    k6part_kernel<<<512, 128>>>();
    finish_kernel<<<BT, 256>>>(x, out);
}